// round 13
// baseline (speedup 1.0000x reference)
#include <cuda_runtime.h>
#include <cuda_fp16.h>
#include <cstdint>
#include <cstddef>

// ---------------- problem constants ----------------
#define MROWS 8192
#define FDIM  1024
#define HDIM  512
#define GDIM  2048
#define KFUSE 1536
#define DSTEPS 8

// ---------------- GEMM tile config ----------------
#define BM 128
#define BN 64
#define BK 32                 // fp16 elems per chunk (64 bytes per row)
#define STAGES 6              // 3 pairs
#define NTHR 256
#define A_TILE_B (BM*64)      // 8192
#define W_TILE_B (BN*64)      // 4096
#define STAGE_B (A_TILE_B + W_TILE_B)    // 12288
#define SMEM_TOTAL (STAGES*STAGE_B)      // 73728

// ---------------- scratch (device globals) ----------------
__device__ __align__(256) __half g_out[(size_t)MROWS*FDIM];     // x-part of A (cls output)
__device__ __align__(256) __half g_h[2][(size_t)MROWS*HDIM];    // double-buffered h
__device__ __align__(256) __half g_wg[(size_t)GDIM*KFUSE];      // gate-permuted fused W (fp16)
__device__ __align__(256) __half g_wc[(size_t)FDIM*HDIM];       // W_cls (fp16)
__device__ __align__(256) float g_biasg[GDIM];                  // permuted b_ih+b_hh
__device__ __align__(256) float g_c[(size_t)MROWS*HDIM];

// ---------------- helpers ----------------
__device__ __forceinline__ uint32_t smem_u32(const void* p) {
    uint32_t a;
    asm("{ .reg .u64 t; cvta.to.shared.u64 t, %1; cvt.u32.u64 %0, t; }" : "=r"(a) : "l"(p));
    return a;
}
__device__ __forceinline__ void cp16(uint32_t dst, const void* src) {
    asm volatile("cp.async.cg.shared.global [%0], [%1], 16;" :: "r"(dst), "l"(src) : "memory");
}
#define CP_COMMIT() asm volatile("cp.async.commit_group;" ::: "memory")
#define CP_WAIT1()  asm volatile("cp.async.wait_group 1;" ::: "memory")

__device__ __forceinline__ void ldsm4(uint32_t addr, uint32_t& r0, uint32_t& r1, uint32_t& r2, uint32_t& r3) {
    asm volatile("ldmatrix.sync.aligned.m8n8.x4.shared.b16 {%0,%1,%2,%3}, [%4];"
                 : "=r"(r0), "=r"(r1), "=r"(r2), "=r"(r3) : "r"(addr));
}
__device__ __forceinline__ void mma16816(float* c, const uint32_t* a, const uint32_t* b) {
    asm("mma.sync.aligned.m16n8k16.row.col.f32.f16.f16.f32 "
        "{%0,%1,%2,%3}, {%4,%5,%6,%7}, {%8,%9}, {%0,%1,%2,%3};"
        : "+f"(c[0]), "+f"(c[1]), "+f"(c[2]), "+f"(c[3])
        : "r"(a[0]), "r"(a[1]), "r"(a[2]), "r"(a[3]), "r"(b[0]), "r"(b[1]));
}
__device__ __forceinline__ float sigmoidf_(float x) { return 1.0f / (1.0f + __expf(-x)); }

// swizzled byte offset within an Nx64B tile: row r, 16B chunk c (0..3)
__device__ __forceinline__ uint32_t swz(int r, int c) {
    return (uint32_t)(r * 64 + ((c ^ ((r >> 1) & 3)) << 4));
}

// ---------------- single-pass fp16 HMMA GEMM (+ fused LSTM cell) ----------------
// CTA tile 128x64, 8 warps of 32x32, 3 CTAs/SM. BK=32, 6 stages (3 pairs),
// ONE barrier + ONE cp.async wait per 2 chunks.
// A operand per chunk: chunk < xchunks -> Ax (ldax), else Ah (HDIM ld, k rebased).
// mode 0 (gates): gate-permuted output; epilogue applies LSTM cell, updates cstate,
//                 writes h (fp16) into hw [MROWS x HDIM]
// mode 1 (cls):   writes Co (ld DSTEPS*FDIM) and fp16 copy to ox [MROWS x FDIM]
__global__ void __launch_bounds__(NTHR, 3)
gemm_hmma(const __half* __restrict__ Ax, int ldax,
          const __half* __restrict__ Ah, int xchunks,
          const __half* __restrict__ W, int ldw,
          int K,
          const float* __restrict__ bias,
          float* __restrict__ cstate,
          float* __restrict__ Co,
          __half* __restrict__ ox,
          __half* __restrict__ hw,
          int mode, int first)
{
    extern __shared__ char smem[];
    const uint32_t sb = smem_u32(smem);
    const int tid = threadIdx.x;
    const int lane = tid & 31;
    const int wid = tid >> 5;
    const int wm = wid & 3;        // 0..3 -> 32-row slice
    const int wn = wid >> 2;       // 0..1 -> 32-col slice
    const int bm = blockIdx.y, bn = blockIdx.x;
    const int nch = K / BK;        // always even here (16, 32, 48)
    const int npair = nch >> 1;

    // loader precompute
    const int r0g = tid >> 2, c0g = tid & 3;
    const uint32_t dOff = swz(r0g, c0g);
    const size_t ldxb = (size_t)ldax * 2;
    const size_t ldhb = (size_t)HDIM * 2;
    const size_t ldwb = (size_t)ldw * 2;
    const char* pX = (const char*)Ax + (size_t)(bm * BM + r0g) * ldxb + c0g * 16;
    const char* pH = Ah ? (const char*)Ah + (size_t)(bm * BM + r0g) * ldhb + c0g * 16 : nullptr;
    const char* pW = (const char*)W + (size_t)(bn * BN + r0g) * ldwb + c0g * 16;
    const size_t ldx64 = ldxb * 64, ldh64 = ldhb * 64;

    auto load_stage = [&](int slot, int chunk) {
        const uint32_t stg = sb + slot * STAGE_B;
        const bool useH = (chunk >= xchunks);
        const char* a = useH ? pH : pX;
        const size_t lda64 = useH ? ldh64 : ldx64;
        const size_t kba = (size_t)(useH ? (chunk - xchunks) : chunk) * 64;
        const size_t kbw = (size_t)chunk * 64;
        cp16(stg + dOff,               a + kba);
        cp16(stg + dOff + 4096,        a + kba + lda64);
        cp16(stg + A_TILE_B + dOff,    pW + kbw);
    };

    float acc[2][4][4];
#pragma unroll
    for (int mt = 0; mt < 2; mt++)
#pragma unroll
        for (int nt = 0; nt < 4; nt++)
#pragma unroll
            for (int e = 0; e < 4; e++) acc[mt][nt][e] = 0.0f;

    // prologue: pairs 0 and 1
    load_stage(0, 0); load_stage(1, 1); CP_COMMIT();
    load_stage(2, 2); load_stage(3, 3); CP_COMMIT();

    const int lrow = lane & 15;
    const int lchk = lane >> 4;

    // loop-invariant swizzled ldmatrix offsets per kh half
    uint32_t offA[2][2], offW[2][2];
#pragma unroll
    for (int kh = 0; kh < 2; kh++) {
        const int cc = kh * 2 + lchk;
#pragma unroll
        for (int mt = 0; mt < 2; mt++)
            offA[kh][mt] = swz(wm * 32 + mt * 16 + lrow, cc);
#pragma unroll
        for (int np = 0; np < 2; np++)
            offW[kh][np] = swz(wn * 32 + np * 16 + lrow, cc);
    }

    int pslot = 0;   // (j % 3) * 2
    for (int j = 0; j < npair; j++) {
        CP_WAIT1();                 // pair j complete (pair j+1 may be pending)
        __syncthreads();            // all warps done with pair j-1 -> its slots reusable
        {
            const int c0 = 2 * j + 4;
            if (c0 < nch) {
                const int s = (pslot + 4 >= STAGES * 1) ? (pslot + 4 - STAGES) : (pslot + 4);
                // slots of pair j+2 == slots of pair j-1 (mod 3 pairs)
                load_stage(s, c0);
                load_stage(s + 1, c0 + 1);
            }
        }
        CP_COMMIT();

#pragma unroll
        for (int half = 0; half < 2; half++) {
            const uint32_t stg = sb + (pslot + half) * STAGE_B;
            const uint32_t sA = stg;
            const uint32_t sW = stg + A_TILE_B;
#pragma unroll
            for (int kh = 0; kh < 2; kh++) {
                uint32_t b[4][2], a[2][4];
#pragma unroll
                for (int np = 0; np < 2; np++) {
                    uint32_t r0, r1, r2, r3;
                    ldsm4(sW + offW[kh][np], r0, r1, r2, r3);
                    b[np * 2][0] = r0; b[np * 2 + 1][0] = r1;
                    b[np * 2][1] = r2; b[np * 2 + 1][1] = r3;
                }
#pragma unroll
                for (int mt = 0; mt < 2; mt++)
                    ldsm4(sA + offA[kh][mt], a[mt][0], a[mt][1], a[mt][2], a[mt][3]);
#pragma unroll
                for (int mt = 0; mt < 2; mt++)
#pragma unroll
                    for (int nt = 0; nt < 4; nt++)
                        mma16816(acc[mt][nt], a[mt], b[nt]);
            }
        }
        pslot = (pslot + 2 == STAGES) ? 0 : pslot + 2;
    }

    // ---------------- epilogue ----------------
    const int rbase = bm * BM + wm * 32;
    const int cbase = bn * BN + wn * 32;
    const int qr = lane >> 2;            // 0..7
    const int qc = (lane & 3) * 2;       // 0,2,4,6

    if (mode == 0) {
        // gate-permuted columns: p = j*4 + gate (i,f,g,o). Even lane holds (p,p+1)=(i,f),
        // odd partner holds (p+2,p+3)=(g,o); shfl_xor(1) assembles the quad.
#pragma unroll
        for (int mt = 0; mt < 2; mt++) {
#pragma unroll
            for (int nt = 0; nt < 4; nt++) {
                const int p = cbase + nt * 8 + qc;
                const float bv0 = bias[p], bv1 = bias[p + 1];
                const float v0 = acc[mt][nt][0] + bv0;
                const float v1 = acc[mt][nt][1] + bv1;
                const float v2 = acc[mt][nt][2] + bv0;
                const float v3 = acc[mt][nt][3] + bv1;
                const float x0 = __shfl_xor_sync(0xffffffffu, v0, 1);
                const float x1 = __shfl_xor_sync(0xffffffffu, v1, 1);
                const float x2 = __shfl_xor_sync(0xffffffffu, v2, 1);
                const float x3 = __shfl_xor_sync(0xffffffffu, v3, 1);
                if (!(lane & 1)) {
                    const int j2 = p >> 2;           // hidden unit
                    const int r0 = rbase + mt * 16 + qr;
#pragma unroll
                    for (int half = 0; half < 2; half++) {
                        const int row = r0 + half * 8;
                        const float iv = half ? v2 : v0;
                        const float fv = half ? v3 : v1;
                        const float gv = half ? x2 : x0;
                        const float ov = half ? x3 : x1;
                        const float cold = first ? 0.0f : cstate[(size_t)row * HDIM + j2];
                        const float cn = sigmoidf_(fv) * cold + sigmoidf_(iv) * tanhf(gv);
                        cstate[(size_t)row * HDIM + j2] = cn;
                        const float h = sigmoidf_(ov) * tanhf(cn);
                        hw[(size_t)row * HDIM + j2] = __float2half(h);
                    }
                }
            }
        }
    } else {
#pragma unroll
        for (int mt = 0; mt < 2; mt++) {
#pragma unroll
            for (int nt = 0; nt < 4; nt++) {
                const int col = cbase + nt * 8 + qc;
                const float bv0 = bias[col], bv1 = bias[col + 1];
#pragma unroll
                for (int half = 0; half < 2; half++) {
                    const int row = rbase + mt * 16 + qr + half * 8;
                    const float v0 = acc[mt][nt][half * 2 + 0] + bv0;
                    const float v1 = acc[mt][nt][half * 2 + 1] + bv1;
                    *(float2*)(Co + (size_t)row * (DSTEPS * FDIM) + col) = make_float2(v0, v1);
                    *(__half2*)(ox + (size_t)row * FDIM + col) =
                        __halves2half2(__float2half(v0), __float2half(v1));
                }
            }
        }
    }
}

// ---------------- elementwise prep kernels ----------------
__global__ void split_act(const float* __restrict__ x, __half* __restrict__ o)
{
    const int idx = blockIdx.x * blockDim.x + threadIdx.x;   // MROWS*FDIM
    o[idx] = __float2half(x[idx]);
}

// gates weights gate-permuted fp16: output row p = j*4 + gate, src row = gate*H + j
__global__ void split_weights(const float* __restrict__ W_ih, const float* __restrict__ W_hh,
                              const float* __restrict__ W_cls,
                              const float* __restrict__ b_ih, const float* __restrict__ b_hh,
                              __half* __restrict__ wg, __half* __restrict__ wc,
                              float* __restrict__ biasg)
{
    const int idx = blockIdx.x * blockDim.x + threadIdx.x;
    const int NG = GDIM * KFUSE;
    if (idx < NG) {
        const int p = idx / KFUSE, col = idx - p * KFUSE;
        const int src_n = (p & 3) * HDIM + (p >> 2);
        const float v = (col < FDIM) ? W_ih[(size_t)src_n * FDIM + col]
                                     : W_hh[(size_t)src_n * HDIM + (col - FDIM)];
        wg[idx] = __float2half(v);
        if (idx < GDIM) {
            const int sn = (idx & 3) * HDIM + (idx >> 2);
            biasg[idx] = b_ih[sn] + b_hh[sn];
        }
    } else {
        const int i2 = idx - NG;                // FDIM*HDIM
        wc[i2] = __float2half(W_cls[i2]);
    }
}

// ---------------- launch ----------------
extern "C" void kernel_launch(void* const* d_in, const int* in_sizes, int n_in,
                              void* d_out, int out_size)
{
    const float* x     = (const float*)d_in[0];
    const float* W_ih  = (const float*)d_in[1];
    const float* W_hh  = (const float*)d_in[2];
    const float* b_ih  = (const float*)d_in[3];
    const float* b_hh  = (const float*)d_in[4];
    const float* W_cls = (const float*)d_in[5];
    const float* b_cls = (const float*)d_in[6];
    float* out = (float*)d_out;                    // [8192 rows, 8 steps, 1024]

    __half *p_o, *p_wg, *p_wc;
    __half *p_h[2];
    float *p_biasg, *p_c;
    cudaGetSymbolAddress((void**)&p_o, g_out);
    {
        __half* base;
        cudaGetSymbolAddress((void**)&base, g_h);
        p_h[0] = base; p_h[1] = base + (size_t)MROWS * HDIM;
    }
    cudaGetSymbolAddress((void**)&p_wg, g_wg);
    cudaGetSymbolAddress((void**)&p_wc, g_wc);
    cudaGetSymbolAddress((void**)&p_biasg, g_biasg);
    cudaGetSymbolAddress((void**)&p_c, g_c);

    cudaFuncSetAttribute(gemm_hmma, cudaFuncAttributeMaxDynamicSharedMemorySize, SMEM_TOTAL);

    split_act<<<(MROWS * FDIM) / 256, 256>>>(x, p_o);
    split_weights<<<(GDIM * KFUSE + FDIM * HDIM) / 256, 256>>>(W_ih, W_hh, W_cls, b_ih, b_hh,
                                                               p_wg, p_wc, p_biasg);

    const dim3 gridG(GDIM / BN, MROWS / BM);   // (32, 64)
    const dim3 gridC(FDIM / BN, MROWS / BM);   // (16, 64)

    for (int d = 0; d < DSTEPS; d++) {
        const int wb = d & 1;                 // h write buffer
        const int rb = (d + 1) & 1;           // h read buffer (prev step)
        // gates GEMM + fused LSTM cell. Step 0: K=1024 (h0 == 0, skip h chunks).
        const int Kg = (d == 0) ? FDIM : KFUSE;
        gemm_hmma<<<gridG, NTHR, SMEM_TOTAL>>>(p_o, FDIM,
                                               p_h[rb], FDIM / BK,
                                               p_wg, KFUSE,
                                               Kg, p_biasg,
                                               p_c, nullptr,
                                               nullptr,
                                               p_h[wb],
                                               0, d == 0 ? 1 : 0);
        // out = h @ W_cls^T + b_cls -> d_out slice d; fp16 copy into out buffer
        gemm_hmma<<<gridC, NTHR, SMEM_TOTAL>>>(p_h[wb], HDIM,
                                               nullptr, 1 << 30,
                                               p_wc, HDIM,
                                               HDIM, b_cls,
                                               nullptr, out + (size_t)d * FDIM,
                                               p_o,
                                               nullptr,
                                               1, 0);
    }
}

// round 14
// speedup vs baseline: 1.6729x; 1.6729x over previous
#include <cuda_runtime.h>
#include <cuda_fp16.h>
#include <cstdint>
#include <cstddef>

// ---------------- problem constants ----------------
#define MROWS 8192
#define FDIM  1024
#define HDIM  512
#define GDIM  2048
#define DSTEPS 8

// ---------------- GEMM tile config (R10-proven) ----------------
#define BM 128
#define BN 64
#define BK 32                 // fp16 elems per chunk (64 bytes per row)
#define STAGES 4
#define NTHR 256
#define A_TILE_B (BM*64)      // 8192
#define W_TILE_B (BN*64)      // 4096
#define STAGE_B (A_TILE_B + W_TILE_B)    // 12288
#define SMEM_TOTAL (STAGES*STAGE_B)      // 49152

// ---------------- scratch (device globals) ----------------
__device__ __align__(256) __half g_x16[(size_t)MROWS*FDIM];     // x quantized fp16
__device__ __align__(256) __half g_h[2][(size_t)MROWS*HDIM];    // double-buffered h (fp16)
__device__ __align__(256) __half g_wg[(size_t)GDIM*FDIM];       // gate-permuted W_ih (fp16)
__device__ __align__(256) __half g_wgf[(size_t)GDIM*HDIM];      // gate-permuted W_fused (fp16)
__device__ __align__(256) __half g_wc[(size_t)FDIM*HDIM];       // W_cls (fp16)
__device__ __align__(256) __half g_wcT[(size_t)HDIM*FDIM];      // W_cls^T (fp16)
__device__ __align__(256) float g_whhp[(size_t)GDIM*HDIM];      // gate-permuted W_hh (fp32 addend)
__device__ __align__(256) float g_biasg[GDIM];                  // permuted b_ih+b_hh
__device__ __align__(256) float g_biasg2[GDIM];                 // biasg + permuted W_ih @ b_cls
__device__ __align__(256) float g_c[(size_t)MROWS*HDIM];

// ---------------- helpers ----------------
__device__ __forceinline__ uint32_t smem_u32(const void* p) {
    uint32_t a;
    asm("{ .reg .u64 t; cvta.to.shared.u64 t, %1; cvt.u32.u64 %0, t; }" : "=r"(a) : "l"(p));
    return a;
}
__device__ __forceinline__ void cp16(uint32_t dst, const void* src) {
    asm volatile("cp.async.cg.shared.global [%0], [%1], 16;" :: "r"(dst), "l"(src) : "memory");
}
#define CP_COMMIT() asm volatile("cp.async.commit_group;" ::: "memory")
#define CP_WAIT2()  asm volatile("cp.async.wait_group 2;" ::: "memory")

__device__ __forceinline__ void ldsm4(uint32_t addr, uint32_t& r0, uint32_t& r1, uint32_t& r2, uint32_t& r3) {
    asm volatile("ldmatrix.sync.aligned.m8n8.x4.shared.b16 {%0,%1,%2,%3}, [%4];"
                 : "=r"(r0), "=r"(r1), "=r"(r2), "=r"(r3) : "r"(addr));
}
__device__ __forceinline__ void mma16816(float* c, const uint32_t* a, const uint32_t* b) {
    asm("mma.sync.aligned.m16n8k16.row.col.f32.f16.f16.f32 "
        "{%0,%1,%2,%3}, {%4,%5,%6,%7}, {%8,%9}, {%0,%1,%2,%3};"
        : "+f"(c[0]), "+f"(c[1]), "+f"(c[2]), "+f"(c[3])
        : "r"(a[0]), "r"(a[1]), "r"(a[2]), "r"(a[3]), "r"(b[0]), "r"(b[1]));
}
__device__ __forceinline__ float sigmoidf_(float x) { return 1.0f / (1.0f + __expf(-x)); }

// swizzled byte offset within an Nx64B tile: row r, 16B chunk c (0..3)
__device__ __forceinline__ uint32_t swz(int r, int c) {
    return (uint32_t)(r * 64 + ((c ^ ((r >> 1) & 3)) << 4));
}

// ---------------- single-pass fp16 HMMA GEMM (+ fused LSTM cell) ----------------
// CTA tile 128x64, 8 warps of 32x32, 3 CTAs/SM, R10 pipeline (4 stages, wait2).
// mode 0 (gates): gate-permuted output; epilogue applies LSTM cell, updates cstate,
//                 writes h (fp16) into hw [M x HDIM]
// mode 1 (cls):   writes Co fp32 (ld DSTEPS*FDIM)
// mode 2 (prep):  dst16[row*HDIM+col] = fp16(acc + addf32[row*HDIM+col])
__global__ void __launch_bounds__(NTHR, 3)
gemm_hmma(const __half* __restrict__ Ax, int ldax,
          const __half* __restrict__ W, int ldw,
          int K,
          const float* __restrict__ bias,
          float* __restrict__ cstate,
          float* __restrict__ Co,
          const float* __restrict__ addf32,
          __half* __restrict__ dst16,
          __half* __restrict__ hw,
          int mode, int first)
{
    extern __shared__ char smem[];
    const uint32_t sb = smem_u32(smem);
    const int tid = threadIdx.x;
    const int lane = tid & 31;
    const int wid = tid >> 5;
    const int wm = wid & 3;        // 0..3 -> 32-row slice
    const int wn = wid >> 2;       // 0..1 -> 32-col slice
    const int bm = blockIdx.y, bn = blockIdx.x;
    const int nch = K / BK;

    // loader precompute
    const int r0g = tid >> 2, c0g = tid & 3;
    const uint32_t dOff = swz(r0g, c0g);
    const size_t ldab = (size_t)ldax * 2;
    const size_t ldwb = (size_t)ldw * 2;
    const char* pA = (const char*)Ax + (size_t)(bm * BM + r0g) * ldab + c0g * 16;
    const char* pW = (const char*)W + (size_t)(bn * BN + r0g) * ldwb + c0g * 16;
    const size_t lda64 = ldab * 64;

    auto load_stage = [&](int slot, int chunk) {
        const uint32_t stg = sb + slot * STAGE_B;
        const size_t kb = (size_t)chunk * 64;
        cp16(stg + dOff,               pA + kb);
        cp16(stg + dOff + 4096,        pA + kb + lda64);
        cp16(stg + A_TILE_B + dOff,    pW + kb);
    };

    float acc[2][4][4];
#pragma unroll
    for (int mt = 0; mt < 2; mt++)
#pragma unroll
        for (int nt = 0; nt < 4; nt++)
#pragma unroll
            for (int e = 0; e < 4; e++) acc[mt][nt][e] = 0.0f;

    load_stage(0, 0); CP_COMMIT();
    load_stage(1, 1); CP_COMMIT();
    load_stage(2, 2); CP_COMMIT();

    const int lrow = lane & 15;
    const int lchk = lane >> 4;

    // loop-invariant swizzled ldmatrix offsets per kh half
    uint32_t offA[2][2], offW[2][2];
#pragma unroll
    for (int kh = 0; kh < 2; kh++) {
        const int cc = kh * 2 + lchk;
#pragma unroll
        for (int mt = 0; mt < 2; mt++)
            offA[kh][mt] = swz(wm * 32 + mt * 16 + lrow, cc);
#pragma unroll
        for (int np = 0; np < 2; np++)
            offW[kh][np] = swz(wn * 32 + np * 16 + lrow, cc);
    }

    for (int i = 0; i < nch; i++) {
        CP_WAIT2();
        __syncthreads();
        if (i + 3 < nch) load_stage((i + 3) % STAGES, i + 3);
        CP_COMMIT();

        const uint32_t stg = sb + (i % STAGES) * STAGE_B;
        const uint32_t sA = stg;
        const uint32_t sW = stg + A_TILE_B;

#pragma unroll
        for (int kh = 0; kh < 2; kh++) {
            uint32_t b[4][2], a[2][4];
#pragma unroll
            for (int np = 0; np < 2; np++) {
                uint32_t r0, r1, r2, r3;
                ldsm4(sW + offW[kh][np], r0, r1, r2, r3);
                b[np * 2][0] = r0; b[np * 2 + 1][0] = r1;
                b[np * 2][1] = r2; b[np * 2 + 1][1] = r3;
            }
#pragma unroll
            for (int mt = 0; mt < 2; mt++)
                ldsm4(sA + offA[kh][mt], a[mt][0], a[mt][1], a[mt][2], a[mt][3]);
#pragma unroll
            for (int mt = 0; mt < 2; mt++)
#pragma unroll
                for (int nt = 0; nt < 4; nt++)
                    mma16816(acc[mt][nt], a[mt], b[nt]);
        }
        __syncthreads();
    }

    // ---------------- epilogue ----------------
    const int rbase = bm * BM + wm * 32;
    const int cbase = bn * BN + wn * 32;
    const int qr = lane >> 2;            // 0..7
    const int qc = (lane & 3) * 2;       // 0,2,4,6

    if (mode == 0) {
        // gate-permuted columns: p = j*4 + gate (i,f,g,o). Even lane holds (p,p+1)=(i,f),
        // odd partner holds (p+2,p+3)=(g,o); shfl_xor(1) assembles the quad.
#pragma unroll
        for (int mt = 0; mt < 2; mt++) {
#pragma unroll
            for (int nt = 0; nt < 4; nt++) {
                const int p = cbase + nt * 8 + qc;
                const float bv0 = bias[p], bv1 = bias[p + 1];
                const float v0 = acc[mt][nt][0] + bv0;
                const float v1 = acc[mt][nt][1] + bv1;
                const float v2 = acc[mt][nt][2] + bv0;
                const float v3 = acc[mt][nt][3] + bv1;
                const float x0 = __shfl_xor_sync(0xffffffffu, v0, 1);
                const float x1 = __shfl_xor_sync(0xffffffffu, v1, 1);
                const float x2 = __shfl_xor_sync(0xffffffffu, v2, 1);
                const float x3 = __shfl_xor_sync(0xffffffffu, v3, 1);
                if (!(lane & 1)) {
                    const int j = p >> 2;            // hidden unit
                    const int r0 = rbase + mt * 16 + qr;
#pragma unroll
                    for (int half = 0; half < 2; half++) {
                        const int row = r0 + half * 8;
                        const float iv = half ? v2 : v0;
                        const float fv = half ? v3 : v1;
                        const float gv = half ? x2 : x0;
                        const float ov = half ? x3 : x1;
                        const float cold = first ? 0.0f : cstate[(size_t)row * HDIM + j];
                        const float cn = sigmoidf_(fv) * cold + sigmoidf_(iv) * tanhf(gv);
                        cstate[(size_t)row * HDIM + j] = cn;
                        const float h = sigmoidf_(ov) * tanhf(cn);
                        hw[(size_t)row * HDIM + j] = __float2half(h);
                    }
                }
            }
        }
    } else if (mode == 1) {
#pragma unroll
        for (int mt = 0; mt < 2; mt++) {
#pragma unroll
            for (int nt = 0; nt < 4; nt++) {
                const int col = cbase + nt * 8 + qc;
                const float bv0 = bias[col], bv1 = bias[col + 1];
#pragma unroll
                for (int half = 0; half < 2; half++) {
                    const int row = rbase + mt * 16 + qr + half * 8;
                    const float v0 = acc[mt][nt][half * 2 + 0] + bv0;
                    const float v1 = acc[mt][nt][half * 2 + 1] + bv1;
                    *(float2*)(Co + (size_t)row * (DSTEPS * FDIM) + col) = make_float2(v0, v1);
                }
            }
        }
    } else {
        // mode 2: dst16 = fp16(acc + addf32), ld = HDIM
#pragma unroll
        for (int mt = 0; mt < 2; mt++) {
#pragma unroll
            for (int nt = 0; nt < 4; nt++) {
                const int col = cbase + nt * 8 + qc;
#pragma unroll
                for (int half = 0; half < 2; half++) {
                    const int row = rbase + mt * 16 + qr + half * 8;
                    const float v0 = acc[mt][nt][half * 2 + 0] + addf32[(size_t)row * HDIM + col];
                    const float v1 = acc[mt][nt][half * 2 + 1] + addf32[(size_t)row * HDIM + col + 1];
                    *(__half2*)(dst16 + (size_t)row * HDIM + col) =
                        __halves2half2(__float2half(v0), __float2half(v1));
                }
            }
        }
    }
}

// ---------------- elementwise prep kernels ----------------
__global__ void split_act(const float* __restrict__ x, __half* __restrict__ o)
{
    const int idx = blockIdx.x * blockDim.x + threadIdx.x;   // MROWS*FDIM
    o[idx] = __float2half(x[idx]);
}

// regions: [0, G*F): wg (+biasg); [G*F, G*F+G*H): whhp; rest: wc + wcT
__global__ void split_weights(const float* __restrict__ W_ih, const float* __restrict__ W_hh,
                              const float* __restrict__ W_cls,
                              const float* __restrict__ b_ih, const float* __restrict__ b_hh,
                              __half* __restrict__ wg, float* __restrict__ whhp,
                              __half* __restrict__ wc, __half* __restrict__ wcT,
                              float* __restrict__ biasg)
{
    const int idx = blockIdx.x * blockDim.x + threadIdx.x;
    const int N1 = GDIM * FDIM;
    const int N2 = GDIM * HDIM;
    if (idx < N1) {
        const int p = idx / FDIM, col = idx - p * FDIM;
        const int src_n = (p & 3) * HDIM + (p >> 2);
        wg[idx] = __float2half(W_ih[(size_t)src_n * FDIM + col]);
        if (idx < GDIM) {
            const int sn = (idx & 3) * HDIM + (idx >> 2);
            biasg[idx] = b_ih[sn] + b_hh[sn];
        }
    } else if (idx < N1 + N2) {
        const int i = idx - N1;
        const int p = i / HDIM, j = i - p * HDIM;
        const int src_n = (p & 3) * HDIM + (p >> 2);
        whhp[i] = W_hh[(size_t)src_n * HDIM + j];
    } else {
        const int i2 = idx - N1 - N2;               // FDIM*HDIM
        const int f = i2 / HDIM, j = i2 - f * HDIM;
        const float v = W_cls[i2];
        wc[i2] = __float2half(v);
        wcT[(size_t)j * FDIM + f] = __float2half(v);
    }
}

// biasg2[p] = biasg[p] + dot(W_ih[src_n,:], b_cls)   (one warp per p)
__global__ void bias_comb(const float* __restrict__ W_ih, const float* __restrict__ b_cls,
                          const float* __restrict__ biasg, float* __restrict__ biasg2)
{
    const int p = blockIdx.x * (blockDim.x >> 5) + (threadIdx.x >> 5);
    const int lane = threadIdx.x & 31;
    const int sn = (p & 3) * HDIM + (p >> 2);
    const float* row = W_ih + (size_t)sn * FDIM;
    float s = 0.0f;
    for (int f = lane; f < FDIM; f += 32) s += row[f] * b_cls[f];
#pragma unroll
    for (int o = 16; o; o >>= 1) s += __shfl_xor_sync(0xffffffffu, s, o);
    if (!lane) biasg2[p] = biasg[p] + s;
}

// ---------------- launch ----------------
extern "C" void kernel_launch(void* const* d_in, const int* in_sizes, int n_in,
                              void* d_out, int out_size)
{
    const float* x     = (const float*)d_in[0];
    const float* W_ih  = (const float*)d_in[1];
    const float* W_hh  = (const float*)d_in[2];
    const float* b_ih  = (const float*)d_in[3];
    const float* b_hh  = (const float*)d_in[4];
    const float* W_cls = (const float*)d_in[5];
    const float* b_cls = (const float*)d_in[6];
    float* out = (float*)d_out;                    // [8192 rows, 8 steps, 1024]

    __half *p_x16, *p_wg, *p_wgf, *p_wc, *p_wcT;
    __half *p_h[2];
    float *p_whhp, *p_biasg, *p_biasg2, *p_c;
    cudaGetSymbolAddress((void**)&p_x16, g_x16);
    {
        __half* base;
        cudaGetSymbolAddress((void**)&base, g_h);
        p_h[0] = base; p_h[1] = base + (size_t)MROWS * HDIM;
    }
    cudaGetSymbolAddress((void**)&p_wg,  g_wg);
    cudaGetSymbolAddress((void**)&p_wgf, g_wgf);
    cudaGetSymbolAddress((void**)&p_wc,  g_wc);
    cudaGetSymbolAddress((void**)&p_wcT, g_wcT);
    cudaGetSymbolAddress((void**)&p_whhp, g_whhp);
    cudaGetSymbolAddress((void**)&p_biasg, g_biasg);
    cudaGetSymbolAddress((void**)&p_biasg2, g_biasg2);
    cudaGetSymbolAddress((void**)&p_c, g_c);

    cudaFuncSetAttribute(gemm_hmma, cudaFuncAttributeMaxDynamicSharedMemorySize, SMEM_TOTAL);

    // prep
    split_act<<<(MROWS * FDIM) / 256, 256>>>(x, p_x16);
    split_weights<<<(GDIM * FDIM + GDIM * HDIM + FDIM * HDIM) / 256, 256>>>(
        W_ih, W_hh, W_cls, b_ih, b_hh, p_wg, p_whhp, p_wc, p_wcT, p_biasg);
    bias_comb<<<GDIM / 8, 256>>>(W_ih, b_cls, p_biasg, p_biasg2);
    // W_fused = (permuted W_ih) @ W_cls + permuted W_hh  -> fp16 [2048, 512]
    gemm_hmma<<<dim3(HDIM / BN, GDIM / BM), NTHR, SMEM_TOTAL>>>(
        p_wg, FDIM, p_wcT, FDIM, FDIM,
        nullptr, nullptr, nullptr, p_whhp, p_wgf, nullptr, 2, 0);

    const dim3 gridG(GDIM / BN, MROWS / BM);   // (32, 64)
    const dim3 gridC(FDIM / BN, MROWS / BM);   // (16, 64)

    for (int d = 0; d < DSTEPS; d++) {
        const int wb = d & 1;                 // h write buffer
        const int rb = (d + 1) & 1;           // h read buffer
        if (d == 0) {
            // gates = x @ W_ih^T + biasg ; fused cell -> h[0], c
            gemm_hmma<<<gridG, NTHR, SMEM_TOTAL>>>(
                p_x16, FDIM, p_wg, FDIM, FDIM,
                p_biasg, p_c, nullptr, nullptr, nullptr, p_h[0], 0, 1);
        } else {
            // gates = h_prev @ W_fused^T + biasg2 ; fused cell -> h[wb], c
            gemm_hmma<<<gridG, NTHR, SMEM_TOTAL>>>(
                p_h[rb], HDIM, p_wgf, HDIM, HDIM,
                p_biasg2, p_c, nullptr, nullptr, nullptr, p_h[wb], 0, 0);
        }
        // out_d = h_d @ W_cls^T + b_cls -> d_out slice d (fp32 only)
        gemm_hmma<<<gridC, NTHR, SMEM_TOTAL>>>(
            p_h[wb], HDIM, p_wc, HDIM, HDIM,
            b_cls, nullptr, out + (size_t)d * FDIM, nullptr, nullptr, nullptr, 1, 0);
    }
}

// round 15
// speedup vs baseline: 1.7139x; 1.0245x over previous
#include <cuda_runtime.h>
#include <cuda_fp16.h>
#include <cstdint>
#include <cstddef>

// ---------------- problem constants ----------------
#define MROWS 8192
#define FDIM  1024
#define HDIM  512
#define GDIM  2048
#define DSTEPS 8

// ---------------- GEMM tile config (R10-proven) ----------------
#define BM 128
#define BN 64
#define BK 32                 // fp16 elems per chunk (64 bytes per row)
#define STAGES 4
#define NTHR 256
#define A_TILE_B (BM*64)      // 8192
#define W_TILE_B (BN*64)      // 4096
#define STAGE_B (A_TILE_B + W_TILE_B)    // 12288
#define SMEM_TOTAL (STAGES*STAGE_B)      // 49152

// ---------------- scratch (device globals) ----------------
__device__ __align__(256) __half g_x16[(size_t)MROWS*FDIM];          // x quantized fp16
__device__ __align__(256) __half g_hall[(size_t)DSTEPS*MROWS*HDIM];  // per-step h (fp16)
__device__ __align__(256) __half g_wg[(size_t)GDIM*FDIM];            // gate-permuted W_ih (fp16)
__device__ __align__(256) __half g_wgf[(size_t)GDIM*HDIM];           // gate-permuted W_fused (fp16)
__device__ __align__(256) __half g_wc[(size_t)FDIM*HDIM];            // W_cls (fp16)
__device__ __align__(256) __half g_wcT[(size_t)HDIM*FDIM];           // W_cls^T (fp16)
__device__ __align__(256) float g_whhp[(size_t)GDIM*HDIM];           // gate-permuted W_hh (fp32 addend)
__device__ __align__(256) float g_biasg[GDIM];                       // permuted b_ih+b_hh
__device__ __align__(256) float g_biasg2[GDIM];                      // biasg + permuted W_ih @ b_cls
__device__ __align__(256) float g_c[(size_t)MROWS*HDIM];

// ---------------- helpers ----------------
__device__ __forceinline__ uint32_t smem_u32(const void* p) {
    uint32_t a;
    asm("{ .reg .u64 t; cvta.to.shared.u64 t, %1; cvt.u32.u64 %0, t; }" : "=r"(a) : "l"(p));
    return a;
}
__device__ __forceinline__ void cp16(uint32_t dst, const void* src) {
    asm volatile("cp.async.cg.shared.global [%0], [%1], 16;" :: "r"(dst), "l"(src) : "memory");
}
#define CP_COMMIT() asm volatile("cp.async.commit_group;" ::: "memory")
#define CP_WAIT2()  asm volatile("cp.async.wait_group 2;" ::: "memory")

__device__ __forceinline__ void ldsm4(uint32_t addr, uint32_t& r0, uint32_t& r1, uint32_t& r2, uint32_t& r3) {
    asm volatile("ldmatrix.sync.aligned.m8n8.x4.shared.b16 {%0,%1,%2,%3}, [%4];"
                 : "=r"(r0), "=r"(r1), "=r"(r2), "=r"(r3) : "r"(addr));
}
__device__ __forceinline__ void mma16816(float* c, const uint32_t* a, const uint32_t* b) {
    asm("mma.sync.aligned.m16n8k16.row.col.f32.f16.f16.f32 "
        "{%0,%1,%2,%3}, {%4,%5,%6,%7}, {%8,%9}, {%0,%1,%2,%3};"
        : "+f"(c[0]), "+f"(c[1]), "+f"(c[2]), "+f"(c[3])
        : "r"(a[0]), "r"(a[1]), "r"(a[2]), "r"(a[3]), "r"(b[0]), "r"(b[1]));
}
__device__ __forceinline__ float sigmoidf_(float x) { return 1.0f / (1.0f + __expf(-x)); }

// swizzled byte offset within an Nx64B tile: row r, 16B chunk c (0..3)
__device__ __forceinline__ uint32_t swz(int r, int c) {
    return (uint32_t)(r * 64 + ((c ^ ((r >> 1) & 3)) << 4));
}

// ---------------- single-pass fp16 HMMA GEMM (+ fused LSTM cell) ----------------
// CTA tile 128x64, 8 warps of 32x32, 3 CTAs/SM, R10 pipeline (4 stages, wait2).
// mode 0 (gates): gate-permuted output; epilogue applies LSTM cell, updates cstate,
//                 writes h (fp16) into hw [M x HDIM]
// mode 1 (cls batched): M = DSTEPS*MROWS rows of hall; epilogue decodes (d, row)
//                 from global row and writes Co[row][d][col] (fp32)
// mode 2 (prep):  dst16[row*HDIM+col] = fp16(acc + addf32[row*HDIM+col])
__global__ void __launch_bounds__(NTHR, 3)
gemm_hmma(const __half* __restrict__ Ax, int ldax,
          const __half* __restrict__ W, int ldw,
          int K,
          const float* __restrict__ bias,
          float* __restrict__ cstate,
          float* __restrict__ Co,
          const float* __restrict__ addf32,
          __half* __restrict__ dst16,
          __half* __restrict__ hw,
          int mode, int first)
{
    extern __shared__ char smem[];
    const uint32_t sb = smem_u32(smem);
    const int tid = threadIdx.x;
    const int lane = tid & 31;
    const int wid = tid >> 5;
    const int wm = wid & 3;        // 0..3 -> 32-row slice
    const int wn = wid >> 2;       // 0..1 -> 32-col slice
    const int bm = blockIdx.y, bn = blockIdx.x;
    const int nch = K / BK;

    // loader precompute
    const int r0g = tid >> 2, c0g = tid & 3;
    const uint32_t dOff = swz(r0g, c0g);
    const size_t ldab = (size_t)ldax * 2;
    const size_t ldwb = (size_t)ldw * 2;
    const char* pA = (const char*)Ax + (size_t)(bm * BM + r0g) * ldab + c0g * 16;
    const char* pW = (const char*)W + (size_t)(bn * BN + r0g) * ldwb + c0g * 16;
    const size_t lda64 = ldab * 64;

    auto load_stage = [&](int slot, int chunk) {
        const uint32_t stg = sb + slot * STAGE_B;
        const size_t kb = (size_t)chunk * 64;
        cp16(stg + dOff,               pA + kb);
        cp16(stg + dOff + 4096,        pA + kb + lda64);
        cp16(stg + A_TILE_B + dOff,    pW + kb);
    };

    float acc[2][4][4];
#pragma unroll
    for (int mt = 0; mt < 2; mt++)
#pragma unroll
        for (int nt = 0; nt < 4; nt++)
#pragma unroll
            for (int e = 0; e < 4; e++) acc[mt][nt][e] = 0.0f;

    load_stage(0, 0); CP_COMMIT();
    load_stage(1, 1); CP_COMMIT();
    load_stage(2, 2); CP_COMMIT();

    const int lrow = lane & 15;
    const int lchk = lane >> 4;

    // loop-invariant swizzled ldmatrix offsets per kh half
    uint32_t offA[2][2], offW[2][2];
#pragma unroll
    for (int kh = 0; kh < 2; kh++) {
        const int cc = kh * 2 + lchk;
#pragma unroll
        for (int mt = 0; mt < 2; mt++)
            offA[kh][mt] = swz(wm * 32 + mt * 16 + lrow, cc);
#pragma unroll
        for (int np = 0; np < 2; np++)
            offW[kh][np] = swz(wn * 32 + np * 16 + lrow, cc);
    }

    for (int i = 0; i < nch; i++) {
        CP_WAIT2();
        __syncthreads();
        if (i + 3 < nch) load_stage((i + 3) % STAGES, i + 3);
        CP_COMMIT();

        const uint32_t stg = sb + (i % STAGES) * STAGE_B;
        const uint32_t sA = stg;
        const uint32_t sW = stg + A_TILE_B;

#pragma unroll
        for (int kh = 0; kh < 2; kh++) {
            uint32_t b[4][2], a[2][4];
#pragma unroll
            for (int np = 0; np < 2; np++) {
                uint32_t r0, r1, r2, r3;
                ldsm4(sW + offW[kh][np], r0, r1, r2, r3);
                b[np * 2][0] = r0; b[np * 2 + 1][0] = r1;
                b[np * 2][1] = r2; b[np * 2 + 1][1] = r3;
            }
#pragma unroll
            for (int mt = 0; mt < 2; mt++)
                ldsm4(sA + offA[kh][mt], a[mt][0], a[mt][1], a[mt][2], a[mt][3]);
#pragma unroll
            for (int mt = 0; mt < 2; mt++)
#pragma unroll
                for (int nt = 0; nt < 4; nt++)
                    mma16816(acc[mt][nt], a[mt], b[nt]);
        }
        __syncthreads();
    }

    // ---------------- epilogue ----------------
    const int rbase = bm * BM + wm * 32;
    const int cbase = bn * BN + wn * 32;
    const int qr = lane >> 2;            // 0..7
    const int qc = (lane & 3) * 2;       // 0,2,4,6

    if (mode == 0) {
        // gate-permuted columns: p = j*4 + gate (i,f,g,o). Even lane holds (p,p+1)=(i,f),
        // odd partner holds (p+2,p+3)=(g,o); shfl_xor(1) assembles the quad.
#pragma unroll
        for (int mt = 0; mt < 2; mt++) {
#pragma unroll
            for (int nt = 0; nt < 4; nt++) {
                const int p = cbase + nt * 8 + qc;
                const float bv0 = bias[p], bv1 = bias[p + 1];
                const float v0 = acc[mt][nt][0] + bv0;
                const float v1 = acc[mt][nt][1] + bv1;
                const float v2 = acc[mt][nt][2] + bv0;
                const float v3 = acc[mt][nt][3] + bv1;
                const float x0 = __shfl_xor_sync(0xffffffffu, v0, 1);
                const float x1 = __shfl_xor_sync(0xffffffffu, v1, 1);
                const float x2 = __shfl_xor_sync(0xffffffffu, v2, 1);
                const float x3 = __shfl_xor_sync(0xffffffffu, v3, 1);
                if (!(lane & 1)) {
                    const int j = p >> 2;            // hidden unit
                    const int r0 = rbase + mt * 16 + qr;
#pragma unroll
                    for (int half = 0; half < 2; half++) {
                        const int row = r0 + half * 8;
                        const float iv = half ? v2 : v0;
                        const float fv = half ? v3 : v1;
                        const float gv = half ? x2 : x0;
                        const float ov = half ? x3 : x1;
                        const float cold = first ? 0.0f : cstate[(size_t)row * HDIM + j];
                        const float cn = sigmoidf_(fv) * cold + sigmoidf_(iv) * tanhf(gv);
                        cstate[(size_t)row * HDIM + j] = cn;
                        const float h = sigmoidf_(ov) * tanhf(cn);
                        hw[(size_t)row * HDIM + j] = __float2half(h);
                    }
                }
            }
        }
    } else if (mode == 1) {
        // batched cls: global row R -> (d = R>>13, row = R&8191);
        // Co[row][d][col], out row stride = DSTEPS*FDIM
#pragma unroll
        for (int mt = 0; mt < 2; mt++) {
#pragma unroll
            for (int nt = 0; nt < 4; nt++) {
                const int col = cbase + nt * 8 + qc;
                const float bv0 = bias[col], bv1 = bias[col + 1];
#pragma unroll
                for (int half = 0; half < 2; half++) {
                    const int R = rbase + mt * 16 + qr + half * 8;
                    const int d = R >> 13;           // / MROWS
                    const int row = R & (MROWS - 1);
                    const float v0 = acc[mt][nt][half * 2 + 0] + bv0;
                    const float v1 = acc[mt][nt][half * 2 + 1] + bv1;
                    *(float2*)(Co + (size_t)row * (DSTEPS * FDIM) + d * FDIM + col) =
                        make_float2(v0, v1);
                }
            }
        }
    } else {
        // mode 2: dst16 = fp16(acc + addf32), ld = HDIM
#pragma unroll
        for (int mt = 0; mt < 2; mt++) {
#pragma unroll
            for (int nt = 0; nt < 4; nt++) {
                const int col = cbase + nt * 8 + qc;
#pragma unroll
                for (int half = 0; half < 2; half++) {
                    const int row = rbase + mt * 16 + qr + half * 8;
                    const float v0 = acc[mt][nt][half * 2 + 0] + addf32[(size_t)row * HDIM + col];
                    const float v1 = acc[mt][nt][half * 2 + 1] + addf32[(size_t)row * HDIM + col + 1];
                    *(__half2*)(dst16 + (size_t)row * HDIM + col) =
                        __halves2half2(__float2half(v0), __float2half(v1));
                }
            }
        }
    }
}

// ---------------- elementwise prep kernels ----------------
__global__ void split_act(const float* __restrict__ x, __half* __restrict__ o)
{
    const int idx = blockIdx.x * blockDim.x + threadIdx.x;   // MROWS*FDIM
    o[idx] = __float2half(x[idx]);
}

// regions: [0, G*F): wg (+biasg); [G*F, G*F+G*H): whhp; rest: wc + wcT
__global__ void split_weights(const float* __restrict__ W_ih, const float* __restrict__ W_hh,
                              const float* __restrict__ W_cls,
                              const float* __restrict__ b_ih, const float* __restrict__ b_hh,
                              __half* __restrict__ wg, float* __restrict__ whhp,
                              __half* __restrict__ wc, __half* __restrict__ wcT,
                              float* __restrict__ biasg)
{
    const int idx = blockIdx.x * blockDim.x + threadIdx.x;
    const int N1 = GDIM * FDIM;
    const int N2 = GDIM * HDIM;
    if (idx < N1) {
        const int p = idx / FDIM, col = idx - p * FDIM;
        const int src_n = (p & 3) * HDIM + (p >> 2);
        wg[idx] = __float2half(W_ih[(size_t)src_n * FDIM + col]);
        if (idx < GDIM) {
            const int sn = (idx & 3) * HDIM + (idx >> 2);
            biasg[idx] = b_ih[sn] + b_hh[sn];
        }
    } else if (idx < N1 + N2) {
        const int i = idx - N1;
        const int p = i / HDIM, j = i - p * HDIM;
        const int src_n = (p & 3) * HDIM + (p >> 2);
        whhp[i] = W_hh[(size_t)src_n * HDIM + j];
    } else {
        const int i2 = idx - N1 - N2;               // FDIM*HDIM
        const int f = i2 / HDIM, j = i2 - f * HDIM;
        const float v = W_cls[i2];
        wc[i2] = __float2half(v);
        wcT[(size_t)j * FDIM + f] = __float2half(v);
    }
}

// biasg2[p] = biasg[p] + dot(W_ih[src_n,:], b_cls)   (one warp per p)
__global__ void bias_comb(const float* __restrict__ W_ih, const float* __restrict__ b_cls,
                          const float* __restrict__ biasg, float* __restrict__ biasg2)
{
    const int p = blockIdx.x * (blockDim.x >> 5) + (threadIdx.x >> 5);
    const int lane = threadIdx.x & 31;
    const int sn = (p & 3) * HDIM + (p >> 2);
    const float* row = W_ih + (size_t)sn * FDIM;
    float s = 0.0f;
    for (int f = lane; f < FDIM; f += 32) s += row[f] * b_cls[f];
#pragma unroll
    for (int o = 16; o; o >>= 1) s += __shfl_xor_sync(0xffffffffu, s, o);
    if (!lane) biasg2[p] = biasg[p] + s;
}

// ---------------- launch ----------------
extern "C" void kernel_launch(void* const* d_in, const int* in_sizes, int n_in,
                              void* d_out, int out_size)
{
    const float* x     = (const float*)d_in[0];
    const float* W_ih  = (const float*)d_in[1];
    const float* W_hh  = (const float*)d_in[2];
    const float* b_ih  = (const float*)d_in[3];
    const float* b_hh  = (const float*)d_in[4];
    const float* W_cls = (const float*)d_in[5];
    const float* b_cls = (const float*)d_in[6];
    float* out = (float*)d_out;                    // [8192 rows, 8 steps, 1024]

    __half *p_x16, *p_hall, *p_wg, *p_wgf, *p_wc, *p_wcT;
    float *p_whhp, *p_biasg, *p_biasg2, *p_c;
    cudaGetSymbolAddress((void**)&p_x16, g_x16);
    cudaGetSymbolAddress((void**)&p_hall, g_hall);
    cudaGetSymbolAddress((void**)&p_wg,  g_wg);
    cudaGetSymbolAddress((void**)&p_wgf, g_wgf);
    cudaGetSymbolAddress((void**)&p_wc,  g_wc);
    cudaGetSymbolAddress((void**)&p_wcT, g_wcT);
    cudaGetSymbolAddress((void**)&p_whhp, g_whhp);
    cudaGetSymbolAddress((void**)&p_biasg, g_biasg);
    cudaGetSymbolAddress((void**)&p_biasg2, g_biasg2);
    cudaGetSymbolAddress((void**)&p_c, g_c);

    cudaFuncSetAttribute(gemm_hmma, cudaFuncAttributeMaxDynamicSharedMemorySize, SMEM_TOTAL);

    // prep
    split_act<<<(MROWS * FDIM) / 256, 256>>>(x, p_x16);
    split_weights<<<(GDIM * FDIM + GDIM * HDIM + FDIM * HDIM) / 256, 256>>>(
        W_ih, W_hh, W_cls, b_ih, b_hh, p_wg, p_whhp, p_wc, p_wcT, p_biasg);
    bias_comb<<<GDIM / 8, 256>>>(W_ih, b_cls, p_biasg, p_biasg2);
    // W_fused = (permuted W_ih) @ W_cls + permuted W_hh  -> fp16 [2048, 512]
    gemm_hmma<<<dim3(HDIM / BN, GDIM / BM), NTHR, SMEM_TOTAL>>>(
        p_wg, FDIM, p_wcT, FDIM, FDIM,
        nullptr, nullptr, nullptr, p_whhp, p_wgf, nullptr, 2, 0);

    const dim3 gridG(GDIM / BN, MROWS / BM);              // (32, 64)
    const size_t HS = (size_t)MROWS * HDIM;               // h slice stride

    // gates chain: h_d written to hall slice d
    gemm_hmma<<<gridG, NTHR, SMEM_TOTAL>>>(
        p_x16, FDIM, p_wg, FDIM, FDIM,
        p_biasg, p_c, nullptr, nullptr, nullptr, p_hall, 0, 1);
    for (int d = 1; d < DSTEPS; d++) {
        gemm_hmma<<<gridG, NTHR, SMEM_TOTAL>>>(
            p_hall + (size_t)(d - 1) * HS, HDIM, p_wgf, HDIM, HDIM,
            p_biasg2, p_c, nullptr, nullptr, nullptr, p_hall + (size_t)d * HS, 0, 0);
    }

    // ONE batched cls GEMM over all steps: M = DSTEPS*MROWS
    const dim3 gridC(FDIM / BN, (DSTEPS * MROWS) / BM);   // (16, 512)
    gemm_hmma<<<gridC, NTHR, SMEM_TOTAL>>>(
        p_hall, HDIM, p_wc, HDIM, HDIM,
        b_cls, nullptr, out, nullptr, nullptr, nullptr, 1, 0);
}

// round 16
// speedup vs baseline: 1.7382x; 1.0142x over previous
#include <cuda_runtime.h>
#include <cuda_fp16.h>
#include <cstdint>
#include <cstddef>

// ---------------- problem constants ----------------
#define MROWS 8192
#define FDIM  1024
#define HDIM  512
#define GDIM  2048
#define DSTEPS 8

// ---------------- GEMM tile config (R10-proven) ----------------
#define BM 128
#define BN 64
#define BK 32                 // fp16 elems per chunk (64 bytes per row)
#define STAGES 4
#define NTHR 256
#define A_TILE_B (BM*64)      // 8192
#define W_TILE_B (BN*64)      // 4096
#define STAGE_B (A_TILE_B + W_TILE_B)    // 12288
#define SMEM_TOTAL (STAGES*STAGE_B)      // 49152

// ---------------- scratch (device globals) ----------------
__device__ __align__(256) __half g_x16[(size_t)MROWS*FDIM];          // x quantized fp16
__device__ __align__(256) __half g_hall[(size_t)DSTEPS*MROWS*HDIM];  // per-step h (fp16)
__device__ __align__(256) __half g_wg[(size_t)GDIM*FDIM];            // gate-permuted W_ih (fp16)
__device__ __align__(256) __half g_wgf[(size_t)GDIM*HDIM];           // gate-permuted W_fused (fp16)
__device__ __align__(256) __half g_wc[(size_t)FDIM*HDIM];            // W_cls (fp16)
__device__ __align__(256) __half g_wcT[(size_t)HDIM*FDIM];           // W_cls^T (fp16)
__device__ __align__(256) float g_whhp[(size_t)GDIM*HDIM];           // gate-permuted W_hh (fp32 addend)
__device__ __align__(256) float g_biasg[GDIM];                       // permuted b_ih+b_hh
__device__ __align__(256) float g_biasg2[GDIM];                      // biasg + permuted W_ih @ b_cls
__device__ __align__(256) float g_c[(size_t)MROWS*HDIM];

// ---------------- helpers ----------------
__device__ __forceinline__ uint32_t smem_u32(const void* p) {
    uint32_t a;
    asm("{ .reg .u64 t; cvta.to.shared.u64 t, %1; cvt.u32.u64 %0, t; }" : "=r"(a) : "l"(p));
    return a;
}
__device__ __forceinline__ void cp16(uint32_t dst, const void* src) {
    asm volatile("cp.async.cg.shared.global [%0], [%1], 16;" :: "r"(dst), "l"(src) : "memory");
}
#define CP_COMMIT() asm volatile("cp.async.commit_group;" ::: "memory")
#define CP_WAIT2()  asm volatile("cp.async.wait_group 2;" ::: "memory")

__device__ __forceinline__ void ldsm4(uint32_t addr, uint32_t& r0, uint32_t& r1, uint32_t& r2, uint32_t& r3) {
    asm volatile("ldmatrix.sync.aligned.m8n8.x4.shared.b16 {%0,%1,%2,%3}, [%4];"
                 : "=r"(r0), "=r"(r1), "=r"(r2), "=r"(r3) : "r"(addr));
}
__device__ __forceinline__ void mma16816(float* c, const uint32_t* a, const uint32_t* b) {
    asm("mma.sync.aligned.m16n8k16.row.col.f32.f16.f16.f32 "
        "{%0,%1,%2,%3}, {%4,%5,%6,%7}, {%8,%9}, {%0,%1,%2,%3};"
        : "+f"(c[0]), "+f"(c[1]), "+f"(c[2]), "+f"(c[3])
        : "r"(a[0]), "r"(a[1]), "r"(a[2]), "r"(a[3]), "r"(b[0]), "r"(b[1]));
}
__device__ __forceinline__ float sigmoidf_(float x) { return 1.0f / (1.0f + __expf(-x)); }

// swizzled byte offset within an Nx64B tile: row r, 16B chunk c (0..3)
__device__ __forceinline__ uint32_t swz(int r, int c) {
    return (uint32_t)(r * 64 + ((c ^ ((r >> 1) & 3)) << 4));
}

// ---------------- single-pass fp16 HMMA GEMM (+ fused LSTM cell) ----------------
// CTA tile 128x64, 8 warps of 32x32, 3 CTAs/SM, R10 pipeline (4 stages, wait2).
// mode 0 (gates): gate-permuted output; epilogue applies LSTM cell, updates cstate,
//                 writes h (fp16) into hw [M x HDIM]
// mode 1 (cls):   writes Co fp32 with row stride DSTEPS*FDIM (per-slice pointer)
// mode 2 (prep):  dst16[row*HDIM+col] = fp16(acc + addf32[row*HDIM+col])
__global__ void __launch_bounds__(NTHR, 3)
gemm_hmma(const __half* __restrict__ Ax, int ldax,
          const __half* __restrict__ W, int ldw,
          int K,
          const float* __restrict__ bias,
          float* __restrict__ cstate,
          float* __restrict__ Co,
          const float* __restrict__ addf32,
          __half* __restrict__ dst16,
          __half* __restrict__ hw,
          int mode, int first)
{
    extern __shared__ char smem[];
    const uint32_t sb = smem_u32(smem);
    const int tid = threadIdx.x;
    const int lane = tid & 31;
    const int wid = tid >> 5;
    const int wm = wid & 3;        // 0..3 -> 32-row slice
    const int wn = wid >> 2;       // 0..1 -> 32-col slice
    const int bm = blockIdx.y, bn = blockIdx.x;
    const int nch = K / BK;

    // loader precompute
    const int r0g = tid >> 2, c0g = tid & 3;
    const uint32_t dOff = swz(r0g, c0g);
    const size_t ldab = (size_t)ldax * 2;
    const size_t ldwb = (size_t)ldw * 2;
    const char* pA = (const char*)Ax + (size_t)(bm * BM + r0g) * ldab + c0g * 16;
    const char* pW = (const char*)W + (size_t)(bn * BN + r0g) * ldwb + c0g * 16;
    const size_t lda64 = ldab * 64;

    auto load_stage = [&](int slot, int chunk) {
        const uint32_t stg = sb + slot * STAGE_B;
        const size_t kb = (size_t)chunk * 64;
        cp16(stg + dOff,               pA + kb);
        cp16(stg + dOff + 4096,        pA + kb + lda64);
        cp16(stg + A_TILE_B + dOff,    pW + kb);
    };

    float acc[2][4][4];
#pragma unroll
    for (int mt = 0; mt < 2; mt++)
#pragma unroll
        for (int nt = 0; nt < 4; nt++)
#pragma unroll
            for (int e = 0; e < 4; e++) acc[mt][nt][e] = 0.0f;

    load_stage(0, 0); CP_COMMIT();
    load_stage(1, 1); CP_COMMIT();
    load_stage(2, 2); CP_COMMIT();

    const int lrow = lane & 15;
    const int lchk = lane >> 4;

    // loop-invariant swizzled ldmatrix offsets per kh half
    uint32_t offA[2][2], offW[2][2];
#pragma unroll
    for (int kh = 0; kh < 2; kh++) {
        const int cc = kh * 2 + lchk;
#pragma unroll
        for (int mt = 0; mt < 2; mt++)
            offA[kh][mt] = swz(wm * 32 + mt * 16 + lrow, cc);
#pragma unroll
        for (int np = 0; np < 2; np++)
            offW[kh][np] = swz(wn * 32 + np * 16 + lrow, cc);
    }

    for (int i = 0; i < nch; i++) {
        CP_WAIT2();
        __syncthreads();
        if (i + 3 < nch) load_stage((i + 3) % STAGES, i + 3);
        CP_COMMIT();

        const uint32_t stg = sb + (i % STAGES) * STAGE_B;
        const uint32_t sA = stg;
        const uint32_t sW = stg + A_TILE_B;

#pragma unroll
        for (int kh = 0; kh < 2; kh++) {
            uint32_t b[4][2], a[2][4];
#pragma unroll
            for (int np = 0; np < 2; np++) {
                uint32_t r0, r1, r2, r3;
                ldsm4(sW + offW[kh][np], r0, r1, r2, r3);
                b[np * 2][0] = r0; b[np * 2 + 1][0] = r1;
                b[np * 2][1] = r2; b[np * 2 + 1][1] = r3;
            }
#pragma unroll
            for (int mt = 0; mt < 2; mt++)
                ldsm4(sA + offA[kh][mt], a[mt][0], a[mt][1], a[mt][2], a[mt][3]);
#pragma unroll
            for (int mt = 0; mt < 2; mt++)
#pragma unroll
                for (int nt = 0; nt < 4; nt++)
                    mma16816(acc[mt][nt], a[mt], b[nt]);
        }
        __syncthreads();
    }

    // ---------------- epilogue ----------------
    const int rbase = bm * BM + wm * 32;
    const int cbase = bn * BN + wn * 32;
    const int qr = lane >> 2;            // 0..7
    const int qc = (lane & 3) * 2;       // 0,2,4,6

    if (mode == 0) {
        // gate-permuted columns: p = j*4 + gate (i,f,g,o). Even lane holds (p,p+1)=(i,f),
        // odd partner holds (p+2,p+3)=(g,o); shfl_xor(1) assembles the quad.
#pragma unroll
        for (int mt = 0; mt < 2; mt++) {
#pragma unroll
            for (int nt = 0; nt < 4; nt++) {
                const int p = cbase + nt * 8 + qc;
                const float bv0 = bias[p], bv1 = bias[p + 1];
                const float v0 = acc[mt][nt][0] + bv0;
                const float v1 = acc[mt][nt][1] + bv1;
                const float v2 = acc[mt][nt][2] + bv0;
                const float v3 = acc[mt][nt][3] + bv1;
                const float x0 = __shfl_xor_sync(0xffffffffu, v0, 1);
                const float x1 = __shfl_xor_sync(0xffffffffu, v1, 1);
                const float x2 = __shfl_xor_sync(0xffffffffu, v2, 1);
                const float x3 = __shfl_xor_sync(0xffffffffu, v3, 1);
                if (!(lane & 1)) {
                    const int j = p >> 2;            // hidden unit
                    const int r0 = rbase + mt * 16 + qr;
#pragma unroll
                    for (int half = 0; half < 2; half++) {
                        const int row = r0 + half * 8;
                        const float iv = half ? v2 : v0;
                        const float fv = half ? v3 : v1;
                        const float gv = half ? x2 : x0;
                        const float ov = half ? x3 : x1;
                        const float cold = first ? 0.0f : cstate[(size_t)row * HDIM + j];
                        const float cn = sigmoidf_(fv) * cold + sigmoidf_(iv) * tanhf(gv);
                        cstate[(size_t)row * HDIM + j] = cn;
                        const float h = sigmoidf_(ov) * tanhf(cn);
                        hw[(size_t)row * HDIM + j] = __float2half(h);
                    }
                }
            }
        }
    } else if (mode == 1) {
#pragma unroll
        for (int mt = 0; mt < 2; mt++) {
#pragma unroll
            for (int nt = 0; nt < 4; nt++) {
                const int col = cbase + nt * 8 + qc;
                const float bv0 = bias[col], bv1 = bias[col + 1];
#pragma unroll
                for (int half = 0; half < 2; half++) {
                    const int row = rbase + mt * 16 + qr + half * 8;
                    const float v0 = acc[mt][nt][half * 2 + 0] + bv0;
                    const float v1 = acc[mt][nt][half * 2 + 1] + bv1;
                    *(float2*)(Co + (size_t)row * (DSTEPS * FDIM) + col) = make_float2(v0, v1);
                }
            }
        }
    } else {
        // mode 2: dst16 = fp16(acc + addf32), ld = HDIM
#pragma unroll
        for (int mt = 0; mt < 2; mt++) {
#pragma unroll
            for (int nt = 0; nt < 4; nt++) {
                const int col = cbase + nt * 8 + qc;
#pragma unroll
                for (int half = 0; half < 2; half++) {
                    const int row = rbase + mt * 16 + qr + half * 8;
                    const float v0 = acc[mt][nt][half * 2 + 0] + addf32[(size_t)row * HDIM + col];
                    const float v1 = acc[mt][nt][half * 2 + 1] + addf32[(size_t)row * HDIM + col + 1];
                    *(__half2*)(dst16 + (size_t)row * HDIM + col) =
                        __halves2half2(__float2half(v0), __float2half(v1));
                }
            }
        }
    }
}

// ---------------- elementwise prep kernels ----------------
__global__ void split_act(const float* __restrict__ x, __half* __restrict__ o)
{
    const int idx = blockIdx.x * blockDim.x + threadIdx.x;   // MROWS*FDIM
    o[idx] = __float2half(x[idx]);
}

// regions: [0, G*F): wg (+biasg); [G*F, G*F+G*H): whhp; rest: wc + wcT
__global__ void split_weights(const float* __restrict__ W_ih, const float* __restrict__ W_hh,
                              const float* __restrict__ W_cls,
                              const float* __restrict__ b_ih, const float* __restrict__ b_hh,
                              __half* __restrict__ wg, float* __restrict__ whhp,
                              __half* __restrict__ wc, __half* __restrict__ wcT,
                              float* __restrict__ biasg)
{
    const int idx = blockIdx.x * blockDim.x + threadIdx.x;
    const int N1 = GDIM * FDIM;
    const int N2 = GDIM * HDIM;
    if (idx < N1) {
        const int p = idx / FDIM, col = idx - p * FDIM;
        const int src_n = (p & 3) * HDIM + (p >> 2);
        wg[idx] = __float2half(W_ih[(size_t)src_n * FDIM + col]);
        if (idx < GDIM) {
            const int sn = (idx & 3) * HDIM + (idx >> 2);
            biasg[idx] = b_ih[sn] + b_hh[sn];
        }
    } else if (idx < N1 + N2) {
        const int i = idx - N1;
        const int p = i / HDIM, j = i - p * HDIM;
        const int src_n = (p & 3) * HDIM + (p >> 2);
        whhp[i] = W_hh[(size_t)src_n * HDIM + j];
    } else {
        const int i2 = idx - N1 - N2;               // FDIM*HDIM
        const int f = i2 / HDIM, j = i2 - f * HDIM;
        const float v = W_cls[i2];
        wc[i2] = __float2half(v);
        wcT[(size_t)j * FDIM + f] = __float2half(v);
    }
}

// biasg2[p] = biasg[p] + dot(W_ih[src_n,:], b_cls)   (one warp per p)
__global__ void bias_comb(const float* __restrict__ W_ih, const float* __restrict__ b_cls,
                          const float* __restrict__ biasg, float* __restrict__ biasg2)
{
    const int p = blockIdx.x * (blockDim.x >> 5) + (threadIdx.x >> 5);
    const int lane = threadIdx.x & 31;
    const int sn = (p & 3) * HDIM + (p >> 2);
    const float* row = W_ih + (size_t)sn * FDIM;
    float s = 0.0f;
    for (int f = lane; f < FDIM; f += 32) s += row[f] * b_cls[f];
#pragma unroll
    for (int o = 16; o; o >>= 1) s += __shfl_xor_sync(0xffffffffu, s, o);
    if (!lane) biasg2[p] = biasg[p] + s;
}

// ---------------- launch ----------------
extern "C" void kernel_launch(void* const* d_in, const int* in_sizes, int n_in,
                              void* d_out, int out_size)
{
    const float* x     = (const float*)d_in[0];
    const float* W_ih  = (const float*)d_in[1];
    const float* W_hh  = (const float*)d_in[2];
    const float* b_ih  = (const float*)d_in[3];
    const float* b_hh  = (const float*)d_in[4];
    const float* W_cls = (const float*)d_in[5];
    const float* b_cls = (const float*)d_in[6];
    float* out = (float*)d_out;                    // [8192 rows, 8 steps, 1024]

    __half *p_x16, *p_hall, *p_wg, *p_wgf, *p_wc, *p_wcT;
    float *p_whhp, *p_biasg, *p_biasg2, *p_c;
    cudaGetSymbolAddress((void**)&p_x16, g_x16);
    cudaGetSymbolAddress((void**)&p_hall, g_hall);
    cudaGetSymbolAddress((void**)&p_wg,  g_wg);
    cudaGetSymbolAddress((void**)&p_wgf, g_wgf);
    cudaGetSymbolAddress((void**)&p_wc,  g_wc);
    cudaGetSymbolAddress((void**)&p_wcT, g_wcT);
    cudaGetSymbolAddress((void**)&p_whhp, g_whhp);
    cudaGetSymbolAddress((void**)&p_biasg, g_biasg);
    cudaGetSymbolAddress((void**)&p_biasg2, g_biasg2);
    cudaGetSymbolAddress((void**)&p_c, g_c);

    cudaFuncSetAttribute(gemm_hmma, cudaFuncAttributeMaxDynamicSharedMemorySize, SMEM_TOTAL);

    // one-time host resources (no device memory): side stream + fork/join events
    static cudaStream_t s2 = nullptr;
    static cudaEvent_t evG[DSTEPS];
    static cudaEvent_t evJoin = nullptr;
    if (!s2) {
        cudaStreamCreateWithFlags(&s2, cudaStreamNonBlocking);
        for (int d = 0; d < DSTEPS; d++)
            cudaEventCreateWithFlags(&evG[d], cudaEventDisableTiming);
        cudaEventCreateWithFlags(&evJoin, cudaEventDisableTiming);
    }

    // prep (main stream)
    split_act<<<(MROWS * FDIM) / 256, 256>>>(x, p_x16);
    split_weights<<<(GDIM * FDIM + GDIM * HDIM + FDIM * HDIM) / 256, 256>>>(
        W_ih, W_hh, W_cls, b_ih, b_hh, p_wg, p_whhp, p_wc, p_wcT, p_biasg);
    bias_comb<<<GDIM / 8, 256>>>(W_ih, b_cls, p_biasg, p_biasg2);
    // W_fused = (permuted W_ih) @ W_cls + permuted W_hh  -> fp16 [2048, 512]
    gemm_hmma<<<dim3(HDIM / BN, GDIM / BM), NTHR, SMEM_TOTAL>>>(
        p_wg, FDIM, p_wcT, FDIM, FDIM,
        nullptr, nullptr, nullptr, p_whhp, p_wgf, nullptr, 2, 0);

    const dim3 gridG(GDIM / BN, MROWS / BM);   // (32, 64)
    const dim3 gridC(FDIM / BN, MROWS / BM);   // (16, 64)
    const size_t HS = (size_t)MROWS * HDIM;    // h slice stride

    for (int d = 0; d < DSTEPS; d++) {
        // gates GEMM + fused cell -> hall slice d (main stream, serial chain)
        if (d == 0) {
            gemm_hmma<<<gridG, NTHR, SMEM_TOTAL>>>(
                p_x16, FDIM, p_wg, FDIM, FDIM,
                p_biasg, p_c, nullptr, nullptr, nullptr, p_hall, 0, 1);
        } else {
            gemm_hmma<<<gridG, NTHR, SMEM_TOTAL>>>(
                p_hall + (size_t)(d - 1) * HS, HDIM, p_wgf, HDIM, HDIM,
                p_biasg2, p_c, nullptr, nullptr, nullptr, p_hall + (size_t)d * HS, 0, 0);
        }
        // fork: cls_d runs on side stream, overlapping gates d+1..
        cudaEventRecord(evG[d], 0);
        cudaStreamWaitEvent(s2, evG[d], 0);
        gemm_hmma<<<gridC, NTHR, SMEM_TOTAL, s2>>>(
            p_hall + (size_t)d * HS, HDIM, p_wc, HDIM, HDIM,
            b_cls, nullptr, out + (size_t)d * FDIM, nullptr, nullptr, nullptr, 1, 0);
    }
    // join: main stream waits for the last cls (s2 launches are in-order)
    cudaEventRecord(evJoin, s2);
    cudaStreamWaitEvent(0, evJoin, 0);
}

// round 17
// speedup vs baseline: 1.7645x; 1.0151x over previous
#include <cuda_runtime.h>
#include <cuda_fp16.h>
#include <cstdint>
#include <cstddef>

// ---------------- problem constants ----------------
#define MROWS 8192
#define FDIM  1024
#define HDIM  512
#define GDIM  2048
#define NCOMB 3072            // GDIM + FDIM (stacked W for combined step)
#define DSTEPS 8

// ---------------- GEMM tile config (R10-proven) ----------------
#define BM 128
#define BN 64
#define BK 32                 // fp16 elems per chunk (64 bytes per row)
#define STAGES 4
#define NTHR 256
#define A_TILE_B (BM*64)      // 8192
#define W_TILE_B (BN*64)      // 4096
#define STAGE_B (A_TILE_B + W_TILE_B)    // 12288
#define SMEM_TOTAL (STAGES*STAGE_B)      // 49152

// ---------------- scratch (device globals) ----------------
__device__ __align__(256) __half g_x16[(size_t)MROWS*FDIM];          // x quantized fp16
__device__ __align__(256) __half g_hall[(size_t)DSTEPS*MROWS*HDIM];  // per-step h (fp16)
__device__ __align__(256) __half g_wg[(size_t)GDIM*FDIM];            // gate-permuted W_ih (fp16)
__device__ __align__(256) __half g_wcomb[(size_t)NCOMB*HDIM];        // [W_fused; W_cls] (fp16)
__device__ __align__(256) __half g_wcT[(size_t)HDIM*FDIM];           // W_cls^T (fp16)
__device__ __align__(256) float g_whhp[(size_t)GDIM*HDIM];           // gate-permuted W_hh (fp32 addend)
__device__ __align__(256) float g_biasg[GDIM];                       // permuted b_ih+b_hh
__device__ __align__(256) float g_biasg2[GDIM];                      // biasg + permuted W_ih @ b_cls
__device__ __align__(256) float g_c[(size_t)MROWS*HDIM];

// ---------------- helpers ----------------
__device__ __forceinline__ uint32_t smem_u32(const void* p) {
    uint32_t a;
    asm("{ .reg .u64 t; cvta.to.shared.u64 t, %1; cvt.u32.u64 %0, t; }" : "=r"(a) : "l"(p));
    return a;
}
__device__ __forceinline__ void cp16(uint32_t dst, const void* src) {
    asm volatile("cp.async.cg.shared.global [%0], [%1], 16;" :: "r"(dst), "l"(src) : "memory");
}
#define CP_COMMIT() asm volatile("cp.async.commit_group;" ::: "memory")
#define CP_WAIT2()  asm volatile("cp.async.wait_group 2;" ::: "memory")

__device__ __forceinline__ void ldsm4(uint32_t addr, uint32_t& r0, uint32_t& r1, uint32_t& r2, uint32_t& r3) {
    asm volatile("ldmatrix.sync.aligned.m8n8.x4.shared.b16 {%0,%1,%2,%3}, [%4];"
                 : "=r"(r0), "=r"(r1), "=r"(r2), "=r"(r3) : "r"(addr));
}
__device__ __forceinline__ void mma16816(float* c, const uint32_t* a, const uint32_t* b) {
    asm("mma.sync.aligned.m16n8k16.row.col.f32.f16.f16.f32 "
        "{%0,%1,%2,%3}, {%4,%5,%6,%7}, {%8,%9}, {%0,%1,%2,%3};"
        : "+f"(c[0]), "+f"(c[1]), "+f"(c[2]), "+f"(c[3])
        : "r"(a[0]), "r"(a[1]), "r"(a[2]), "r"(a[3]), "r"(b[0]), "r"(b[1]));
}
__device__ __forceinline__ float sigmoidf_(float x) { return 1.0f / (1.0f + __expf(-x)); }
__device__ __forceinline__ float tanh_ap(float x) {
    float y;
    asm("tanh.approx.f32 %0, %1;" : "=f"(y) : "f"(x));
    return y;
}

// swizzled byte offset within an Nx64B tile: row r, 16B chunk c (0..3)
__device__ __forceinline__ uint32_t swz(int r, int c) {
    return (uint32_t)(r * 64 + ((c ^ ((r >> 1) & 3)) << 4));
}

// ---------------- single-pass fp16 HMMA GEMM (+ fused LSTM cell + fused cls) ----
// CTA tile 128x64, 8 warps of 32x32, 3 CTAs/SM, R10 pipeline.
// mode 0: columns [0, GDIM) -> gate-permuted LSTM cell epilogue (cstate, hw).
//         columns [GDIM, NCOMB) (if grid.x > 32) -> cls epilogue:
//         Co[row*(DSTEPS*FDIM) + (col-GDIM)] = acc + bias_cls[col-GDIM]
// mode 1: pure cls: Co[row*(DSTEPS*FDIM) + col] = acc + bias[col]
// mode 2 (prep): dst16[row*HDIM+col] = fp16(acc + addf32[row*HDIM+col])
__global__ void __launch_bounds__(NTHR, 3)
gemm_hmma(const __half* __restrict__ Ax, int ldax,
          const __half* __restrict__ W, int ldw,
          int K,
          const float* __restrict__ bias,
          const float* __restrict__ bias_cls,
          float* __restrict__ cstate,
          float* __restrict__ Co,
          const float* __restrict__ addf32,
          __half* __restrict__ dst16,
          __half* __restrict__ hw,
          int mode, int first)
{
    extern __shared__ char smem[];
    const uint32_t sb = smem_u32(smem);
    const int tid = threadIdx.x;
    const int lane = tid & 31;
    const int wid = tid >> 5;
    const int wm = wid & 3;        // 0..3 -> 32-row slice
    const int wn = wid >> 2;       // 0..1 -> 32-col slice
    const int bm = blockIdx.y, bn = blockIdx.x;
    const int nch = K / BK;

    // loader precompute
    const int r0g = tid >> 2, c0g = tid & 3;
    const uint32_t dOff = swz(r0g, c0g);
    const size_t ldab = (size_t)ldax * 2;
    const size_t ldwb = (size_t)ldw * 2;
    const char* pA = (const char*)Ax + (size_t)(bm * BM + r0g) * ldab + c0g * 16;
    const char* pW = (const char*)W + (size_t)(bn * BN + r0g) * ldwb + c0g * 16;
    const size_t lda64 = ldab * 64;

    auto load_stage = [&](int slot, int chunk) {
        const uint32_t stg = sb + slot * STAGE_B;
        const size_t kb = (size_t)chunk * 64;
        cp16(stg + dOff,               pA + kb);
        cp16(stg + dOff + 4096,        pA + kb + lda64);
        cp16(stg + A_TILE_B + dOff,    pW + kb);
    };

    float acc[2][4][4];
#pragma unroll
    for (int mt = 0; mt < 2; mt++)
#pragma unroll
        for (int nt = 0; nt < 4; nt++)
#pragma unroll
            for (int e = 0; e < 4; e++) acc[mt][nt][e] = 0.0f;

    load_stage(0, 0); CP_COMMIT();
    load_stage(1, 1); CP_COMMIT();
    load_stage(2, 2); CP_COMMIT();

    const int lrow = lane & 15;
    const int lchk = lane >> 4;

    // loop-invariant swizzled ldmatrix offsets per kh half
    uint32_t offA[2][2], offW[2][2];
#pragma unroll
    for (int kh = 0; kh < 2; kh++) {
        const int cc = kh * 2 + lchk;
#pragma unroll
        for (int mt = 0; mt < 2; mt++)
            offA[kh][mt] = swz(wm * 32 + mt * 16 + lrow, cc);
#pragma unroll
        for (int np = 0; np < 2; np++)
            offW[kh][np] = swz(wn * 32 + np * 16 + lrow, cc);
    }

    for (int i = 0; i < nch; i++) {
        CP_WAIT2();
        __syncthreads();
        if (i + 3 < nch) load_stage((i + 3) % STAGES, i + 3);
        CP_COMMIT();

        const uint32_t stg = sb + (i % STAGES) * STAGE_B;
        const uint32_t sA = stg;
        const uint32_t sW = stg + A_TILE_B;

#pragma unroll
        for (int kh = 0; kh < 2; kh++) {
            uint32_t b[4][2], a[2][4];
#pragma unroll
            for (int np = 0; np < 2; np++) {
                uint32_t r0, r1, r2, r3;
                ldsm4(sW + offW[kh][np], r0, r1, r2, r3);
                b[np * 2][0] = r0; b[np * 2 + 1][0] = r1;
                b[np * 2][1] = r2; b[np * 2 + 1][1] = r3;
            }
#pragma unroll
            for (int mt = 0; mt < 2; mt++)
                ldsm4(sA + offA[kh][mt], a[mt][0], a[mt][1], a[mt][2], a[mt][3]);
#pragma unroll
            for (int mt = 0; mt < 2; mt++)
#pragma unroll
                for (int nt = 0; nt < 4; nt++)
                    mma16816(acc[mt][nt], a[mt], b[nt]);
        }
        __syncthreads();
    }

    // ---------------- epilogue ----------------
    const int rbase = bm * BM + wm * 32;
    const int cbase = bn * BN + wn * 32;
    const int qr = lane >> 2;            // 0..7
    const int qc = (lane & 3) * 2;       // 0,2,4,6

    const bool cell_cols = (mode == 0) && (bn < GDIM / BN);

    if (cell_cols) {
        // gate-permuted columns: p = j*4 + gate (i,f,g,o). Even lane holds (p,p+1)=(i,f),
        // odd partner holds (p+2,p+3)=(g,o); shfl_xor(1) assembles the quad.
#pragma unroll
        for (int mt = 0; mt < 2; mt++) {
#pragma unroll
            for (int nt = 0; nt < 4; nt++) {
                const int p = cbase + nt * 8 + qc;
                const float bv0 = bias[p], bv1 = bias[p + 1];
                const float v0 = acc[mt][nt][0] + bv0;
                const float v1 = acc[mt][nt][1] + bv1;
                const float v2 = acc[mt][nt][2] + bv0;
                const float v3 = acc[mt][nt][3] + bv1;
                const float x0 = __shfl_xor_sync(0xffffffffu, v0, 1);
                const float x1 = __shfl_xor_sync(0xffffffffu, v1, 1);
                const float x2 = __shfl_xor_sync(0xffffffffu, v2, 1);
                const float x3 = __shfl_xor_sync(0xffffffffu, v3, 1);
                if (!(lane & 1)) {
                    const int j = p >> 2;            // hidden unit
                    const int r0 = rbase + mt * 16 + qr;
#pragma unroll
                    for (int half = 0; half < 2; half++) {
                        const int row = r0 + half * 8;
                        const float iv = half ? v2 : v0;
                        const float fv = half ? v3 : v1;
                        const float gv = half ? x2 : x0;
                        const float ov = half ? x3 : x1;
                        const float cold = first ? 0.0f : cstate[(size_t)row * HDIM + j];
                        const float cn = sigmoidf_(fv) * cold + sigmoidf_(iv) * tanh_ap(gv);
                        cstate[(size_t)row * HDIM + j] = cn;
                        const float h = sigmoidf_(ov) * tanh_ap(cn);
                        hw[(size_t)row * HDIM + j] = __float2half(h);
                    }
                }
            }
        }
    } else if (mode <= 1) {
        // cls columns: mode 1 -> col = cbase; mode 0 combined -> col = cbase - GDIM
        const int coff = (mode == 0) ? GDIM : 0;
        const float* bcls = (mode == 0) ? bias_cls : bias;
#pragma unroll
        for (int mt = 0; mt < 2; mt++) {
#pragma unroll
            for (int nt = 0; nt < 4; nt++) {
                const int col = cbase + nt * 8 + qc - coff;
                const float bv0 = bcls[col], bv1 = bcls[col + 1];
#pragma unroll
                for (int half = 0; half < 2; half++) {
                    const int row = rbase + mt * 16 + qr + half * 8;
                    const float v0 = acc[mt][nt][half * 2 + 0] + bv0;
                    const float v1 = acc[mt][nt][half * 2 + 1] + bv1;
                    *(float2*)(Co + (size_t)row * (DSTEPS * FDIM) + col) = make_float2(v0, v1);
                }
            }
        }
    } else {
        // mode 2: dst16 = fp16(acc + addf32), ld = HDIM
#pragma unroll
        for (int mt = 0; mt < 2; mt++) {
#pragma unroll
            for (int nt = 0; nt < 4; nt++) {
                const int col = cbase + nt * 8 + qc;
#pragma unroll
                for (int half = 0; half < 2; half++) {
                    const int row = rbase + mt * 16 + qr + half * 8;
                    const float v0 = acc[mt][nt][half * 2 + 0] + addf32[(size_t)row * HDIM + col];
                    const float v1 = acc[mt][nt][half * 2 + 1] + addf32[(size_t)row * HDIM + col + 1];
                    *(__half2*)(dst16 + (size_t)row * HDIM + col) =
                        __halves2half2(__float2half(v0), __float2half(v1));
                }
            }
        }
    }
}

// ---------------- elementwise prep kernels ----------------
__global__ void split_act(const float* __restrict__ x, __half* __restrict__ o)
{
    const int idx = blockIdx.x * blockDim.x + threadIdx.x;   // MROWS*FDIM
    o[idx] = __float2half(x[idx]);
}

// regions: [0, G*F): wg (+biasg); [G*F, G*F+G*H): whhp; rest: wcomb cls rows + wcT
__global__ void split_weights(const float* __restrict__ W_ih, const float* __restrict__ W_hh,
                              const float* __restrict__ W_cls,
                              const float* __restrict__ b_ih, const float* __restrict__ b_hh,
                              __half* __restrict__ wg, float* __restrict__ whhp,
                              __half* __restrict__ wcomb, __half* __restrict__ wcT,
                              float* __restrict__ biasg)
{
    const int idx = blockIdx.x * blockDim.x + threadIdx.x;
    const int N1 = GDIM * FDIM;
    const int N2 = GDIM * HDIM;
    if (idx < N1) {
        const int p = idx / FDIM, col = idx - p * FDIM;
        const int src_n = (p & 3) * HDIM + (p >> 2);
        wg[idx] = __float2half(W_ih[(size_t)src_n * FDIM + col]);
        if (idx < GDIM) {
            const int sn = (idx & 3) * HDIM + (idx >> 2);
            biasg[idx] = b_ih[sn] + b_hh[sn];
        }
    } else if (idx < N1 + N2) {
        const int i = idx - N1;
        const int p = i / HDIM, j = i - p * HDIM;
        const int src_n = (p & 3) * HDIM + (p >> 2);
        whhp[i] = W_hh[(size_t)src_n * HDIM + j];
    } else {
        const int i2 = idx - N1 - N2;               // FDIM*HDIM
        const int f = i2 / HDIM, j = i2 - f * HDIM;
        const float v = W_cls[i2];
        wcomb[(size_t)(GDIM + f) * HDIM + j] = __float2half(v);   // cls rows of combined W
        wcT[(size_t)j * FDIM + f] = __float2half(v);
    }
}

// biasg2[p] = biasg[p] + dot(W_ih[src_n,:], b_cls)   (one warp per p)
__global__ void bias_comb(const float* __restrict__ W_ih, const float* __restrict__ b_cls,
                          const float* __restrict__ biasg, float* __restrict__ biasg2)
{
    const int p = blockIdx.x * (blockDim.x >> 5) + (threadIdx.x >> 5);
    const int lane = threadIdx.x & 31;
    const int sn = (p & 3) * HDIM + (p >> 2);
    const float* row = W_ih + (size_t)sn * FDIM;
    float s = 0.0f;
    for (int f = lane; f < FDIM; f += 32) s += row[f] * b_cls[f];
#pragma unroll
    for (int o = 16; o; o >>= 1) s += __shfl_xor_sync(0xffffffffu, s, o);
    if (!lane) biasg2[p] = biasg[p] + s;
}

// ---------------- launch ----------------
extern "C" void kernel_launch(void* const* d_in, const int* in_sizes, int n_in,
                              void* d_out, int out_size)
{
    const float* x     = (const float*)d_in[0];
    const float* W_ih  = (const float*)d_in[1];
    const float* W_hh  = (const float*)d_in[2];
    const float* b_ih  = (const float*)d_in[3];
    const float* b_hh  = (const float*)d_in[4];
    const float* W_cls = (const float*)d_in[5];
    const float* b_cls = (const float*)d_in[6];
    float* out = (float*)d_out;                    // [8192 rows, 8 steps, 1024]

    __half *p_x16, *p_hall, *p_wg, *p_wcomb, *p_wcT;
    float *p_whhp, *p_biasg, *p_biasg2, *p_c;
    cudaGetSymbolAddress((void**)&p_x16, g_x16);
    cudaGetSymbolAddress((void**)&p_hall, g_hall);
    cudaGetSymbolAddress((void**)&p_wg,  g_wg);
    cudaGetSymbolAddress((void**)&p_wcomb, g_wcomb);
    cudaGetSymbolAddress((void**)&p_wcT, g_wcT);
    cudaGetSymbolAddress((void**)&p_whhp, g_whhp);
    cudaGetSymbolAddress((void**)&p_biasg, g_biasg);
    cudaGetSymbolAddress((void**)&p_biasg2, g_biasg2);
    cudaGetSymbolAddress((void**)&p_c, g_c);

    cudaFuncSetAttribute(gemm_hmma, cudaFuncAttributeMaxDynamicSharedMemorySize, SMEM_TOTAL);

    // prep
    split_act<<<(MROWS * FDIM) / 256, 256>>>(x, p_x16);
    split_weights<<<(GDIM * FDIM + GDIM * HDIM + FDIM * HDIM) / 256, 256>>>(
        W_ih, W_hh, W_cls, b_ih, b_hh, p_wg, p_whhp, p_wcomb, p_wcT, p_biasg);
    bias_comb<<<GDIM / 8, 256>>>(W_ih, b_cls, p_biasg, p_biasg2);
    // W_fused = (permuted W_ih) @ W_cls + permuted W_hh -> wcomb rows [0, GDIM)
    gemm_hmma<<<dim3(HDIM / BN, GDIM / BM), NTHR, SMEM_TOTAL>>>(
        p_wg, FDIM, p_wcT, FDIM, FDIM,
        nullptr, nullptr, nullptr, nullptr, p_whhp, p_wcomb, nullptr, 2, 0);

    const size_t HS = (size_t)MROWS * HDIM;    // h slice stride

    // d0: gates only (K=1024, h0 == 0) -> hall slice 0
    gemm_hmma<<<dim3(GDIM / BN, MROWS / BM), NTHR, SMEM_TOTAL>>>(
        p_x16, FDIM, p_wg, FDIM, FDIM,
        p_biasg, nullptr, p_c, nullptr, nullptr, nullptr, p_hall, 0, 1);

    // d = 1..7: combined GEMM on A = h_{d-1}: N = 3072
    //   cols [0,2048)  -> gates_d (cell -> hall slice d, cstate)
    //   cols [2048,3072) -> out_{d-1} = h_{d-1} @ W_cls^T + b_cls
    for (int d = 1; d < DSTEPS; d++) {
        gemm_hmma<<<dim3(NCOMB / BN, MROWS / BM), NTHR, SMEM_TOTAL>>>(
            p_hall + (size_t)(d - 1) * HS, HDIM, p_wcomb, HDIM, HDIM,
            p_biasg2, b_cls, p_c, out + (size_t)(d - 1) * FDIM,
            nullptr, nullptr, p_hall + (size_t)d * HS, 0, 0);
    }

    // final cls for step 7
    gemm_hmma<<<dim3(FDIM / BN, MROWS / BM), NTHR, SMEM_TOTAL>>>(
        p_hall + (size_t)(DSTEPS - 1) * HS, HDIM, p_wcomb + (size_t)GDIM * HDIM, HDIM, HDIM,
        b_cls, nullptr, nullptr, out + (size_t)(DSTEPS - 1) * FDIM,
        nullptr, nullptr, nullptr, 1, 0);
}